// round 1
// baseline (speedup 1.0000x reference)
#include <cuda_runtime.h>
#include <cstdint>

#define N_NODES 100000
#define E_EDGES 200000
#define SDIM 128
#define CDIM 768
#define KTOT 896      // SDIM + CDIM
#define NC_PAD 384    // padded N for combined GEMM (320 used: 192 chem + 128 comb)
#define NS_PAD 128    // padded N for structural GEMM (64 used)

// ---------------- scratch (static device globals; no allocation) ----------------
__device__ float g_AP[(size_t)E_EDGES * KTOT];   // [sp | cp] rows for valid edges (by slot)
__device__ float g_SP[(size_t)E_EDGES * SDIM];   // structural products, all edges
__device__ float g_Hs[(size_t)E_EDGES * NS_PAD]; // structural hidden (pre-relu, bias added)
__device__ float g_Hc[(size_t)E_EDGES * NC_PAD]; // chem+combined hidden (by slot)
__device__ float g_ss[E_EDGES];                  // structural score per edge
__device__ int   g_outidx[E_EDGES];              // slot -> edge id
__device__ float g_WC[KTOT * NC_PAD];            // packed combined weights
__device__ float g_bC[NC_PAD];
__device__ float g_WS[SDIM * NS_PAD];            // padded sw1
__device__ float g_bS[NS_PAD];
__device__ float g_w[3];                         // softmaxed path weights
__device__ int   g_count;
__device__ int   g_is64;

// ---------------- packed fp32x2 helpers ----------------
__device__ __forceinline__ unsigned long long pack2(float lo, float hi) {
    unsigned long long r;
    asm("mov.b64 %0, {%1, %2};" : "=l"(r) : "f"(lo), "f"(hi));
    return r;
}
__device__ __forceinline__ unsigned long long fma2(unsigned long long a, unsigned long long b,
                                                   unsigned long long c) {
    unsigned long long d;
    asm("fma.rn.f32x2 %0, %1, %2, %3;" : "=l"(d) : "l"(a), "l"(b), "l"(c));
    return d;
}
__device__ __forceinline__ float2 unpack2(unsigned long long v) {
    float lo, hi;
    asm("mov.b64 {%0, %1}, %2;" : "=f"(lo), "=f"(hi) : "l"(v));
    return make_float2(lo, hi);
}

__device__ __forceinline__ void read_edge(const void* edge, int e, int& s, int& d) {
    if (g_is64) {
        const long long* p = (const long long*)edge;
        s = (int)p[2 * e]; d = (int)p[2 * e + 1];
    } else {
        const int* p = (const int*)edge;
        s = p[2 * e]; d = p[2 * e + 1];
    }
}

// ---------------- kernel 0: pack weights, reset counter, detect dtypes ----------------
__global__ void k_pack(const float* __restrict__ cw1, const float* __restrict__ cb1,
                       const float* __restrict__ mw1, const float* __restrict__ mb1,
                       const float* __restrict__ sw1, const float* __restrict__ sb1,
                       const float* __restrict__ pw, const void* __restrict__ edge)
{
    int idx = blockIdx.x * blockDim.x + threadIdx.x;
    const int totC = KTOT * NC_PAD;
    if (idx < totC) {
        int k = idx / NC_PAD, n = idx % NC_PAD;
        float v = 0.0f;
        if (n < 192) {
            if (k >= SDIM) v = cw1[(k - SDIM) * 192 + n];
        } else if (n < 320) {
            v = mw1[k * 128 + (n - 192)];
        }
        g_WC[idx] = v;
    }
    int idx2 = idx - totC;
    if (idx2 >= 0 && idx2 < SDIM * NS_PAD) {
        int k = idx2 / NS_PAD, n = idx2 % NS_PAD;
        g_WS[idx2] = (n < 64) ? sw1[k * 64 + n] : 0.0f;
    }
    if (idx < NC_PAD) g_bC[idx] = (idx < 192) ? cb1[idx] : (idx < 320 ? mb1[idx - 192] : 0.0f);
    if (idx < NS_PAD) g_bS[idx] = (idx < 64) ? sb1[idx] : 0.0f;
    if (idx == 0) {
        g_count = 0;
        // int64-vs-int32 edge detection: for int64 (ids < 2^31) all high words are 0.
        const unsigned* ew = (const unsigned*)edge;
        unsigned hi = 0;
        #pragma unroll
        for (int i = 0; i < 16; i++) hi |= ew[2 * i + 1];
        g_is64 = (hi == 0u) ? 1 : 0;
        float p0 = pw[0], p1 = pw[1], p2 = pw[2];
        float m = fmaxf(p0, fmaxf(p1, p2));
        float e0 = expf(p0 - m), e1 = expf(p1 - m), e2 = expf(p2 - m);
        float s = e0 + e1 + e2;
        g_w[0] = e0 / s; g_w[1] = e1 / s; g_w[2] = e2 / s;
    }
}

// ---------------- kernel 1: gather products, compact valid edges ----------------
__global__ void k_gather(const float* __restrict__ z, const float* __restrict__ chem,
                         const void* __restrict__ edge, const int* __restrict__ mask)
{
    int w = (blockIdx.x * blockDim.x + threadIdx.x) >> 5;
    int lane = threadIdx.x & 31;
    if (w >= E_EDGES) return;

    int src = 0, dst = 0, valid = 0;
    if (lane == 0) {
        read_edge(edge, w, src, dst);
        valid = (mask[src] != 0) && (mask[dst] != 0);
    }
    src = __shfl_sync(0xffffffffu, src, 0);
    dst = __shfl_sync(0xffffffffu, dst, 0);
    valid = __shfl_sync(0xffffffffu, valid, 0);

    float4 zs = *(const float4*)&z[(size_t)src * SDIM + lane * 4];
    float4 zd = *(const float4*)&z[(size_t)dst * SDIM + lane * 4];
    float4 p;
    p.x = zs.x * zd.x; p.y = zs.y * zd.y; p.z = zs.z * zd.z; p.w = zs.w * zd.w;
    *(float4*)&g_SP[(size_t)w * SDIM + lane * 4] = p;

    if (!valid) return;

    int slot = 0;
    if (lane == 0) slot = atomicAdd(&g_count, 1);
    slot = __shfl_sync(0xffffffffu, slot, 0);
    if (lane == 0) g_outidx[slot] = w;

    size_t ap = (size_t)slot * KTOT;
    *(float4*)&g_AP[ap + lane * 4] = p;
    #pragma unroll
    for (int i = 0; i < 6; i++) {
        int col = (lane + 32 * i) * 4;
        float4 cs = *(const float4*)&chem[(size_t)src * CDIM + col];
        float4 cd = *(const float4*)&chem[(size_t)dst * CDIM + col];
        float4 c;
        c.x = cs.x * cd.x; c.y = cs.y * cd.y; c.z = cs.z * cd.z; c.w = cs.w * cd.w;
        *(float4*)&g_AP[ap + SDIM + col] = c;
    }
}

// ---------------- tiled SGEMM with packed f32x2 FMA ----------------
// BM=BN=128, BK=16, 256 threads, 8x8 micro-tile (rows ty*4..+3 & 64+ty*4..+3,
// cols tx*4..+3 & 64+tx*4..+3). MODE 0: structural, MODE 1: combined.
template <int MODE>
__global__ void __launch_bounds__(256) k_sgemm()
{
    const float* A;  const float* B;  const float* bias;  float* C;
    int lda, ldb, ldc, K, M;
    if (MODE == 0) {
        A = g_SP; lda = SDIM; B = g_WS; ldb = NS_PAD; bias = g_bS;
        C = g_Hs; ldc = NS_PAD; K = SDIM; M = E_EDGES;
    } else {
        A = g_AP; lda = KTOT; B = g_WC; ldb = NC_PAD; bias = g_bC;
        C = g_Hc; ldc = NC_PAD; K = KTOT; M = g_count;
    }
    int m0 = blockIdx.x * 128;
    if (m0 >= M) return;
    int n0 = blockIdx.y * 128;

    __shared__ float As[16][132];
    __shared__ float Bs[16][128];

    int tx = threadIdx.x & 15;
    int ty = threadIdx.x >> 4;

    unsigned long long cc[8][4];
    #pragma unroll
    for (int i = 0; i < 8; i++)
        #pragma unroll
        for (int j = 0; j < 4; j++) cc[i][j] = 0ull;

    for (int k0 = 0; k0 < K; k0 += 16) {
        #pragma unroll
        for (int i = 0; i < 2; i++) {
            int id = threadIdx.x + i * 256;
            int row = id >> 2, kq = (id & 3) << 2;
            float4 v = make_float4(0.f, 0.f, 0.f, 0.f);
            if (m0 + row < M) v = *(const float4*)&A[(size_t)(m0 + row) * lda + k0 + kq];
            As[kq + 0][row] = v.x; As[kq + 1][row] = v.y;
            As[kq + 2][row] = v.z; As[kq + 3][row] = v.w;
        }
        #pragma unroll
        for (int i = 0; i < 2; i++) {
            int id = threadIdx.x + i * 256;
            int kk = id >> 5, nq = (id & 31) << 2;
            *(float4*)&Bs[kk][nq] = *(const float4*)&B[(size_t)(k0 + kk) * ldb + n0 + nq];
        }
        __syncthreads();
        #pragma unroll
        for (int k = 0; k < 16; k++) {
            float4 a0 = *(const float4*)&As[k][ty * 4];
            float4 a1 = *(const float4*)&As[k][64 + ty * 4];
            float4 b0 = *(const float4*)&Bs[k][tx * 4];
            float4 b1 = *(const float4*)&Bs[k][64 + tx * 4];
            float av[8] = {a0.x, a0.y, a0.z, a0.w, a1.x, a1.y, a1.z, a1.w};
            unsigned long long bp[4];
            bp[0] = pack2(b0.x, b0.y); bp[1] = pack2(b0.z, b0.w);
            bp[2] = pack2(b1.x, b1.y); bp[3] = pack2(b1.z, b1.w);
            #pragma unroll
            for (int i = 0; i < 8; i++) {
                unsigned long long ad = pack2(av[i], av[i]);
                #pragma unroll
                for (int j = 0; j < 4; j++) cc[i][j] = fma2(ad, bp[j], cc[i][j]);
            }
        }
        __syncthreads();
    }

    float4 bv0 = *(const float4*)&bias[n0 + tx * 4];
    float4 bv1 = *(const float4*)&bias[n0 + 64 + tx * 4];
    #pragma unroll
    for (int i = 0; i < 8; i++) {
        int m = (i < 4) ? (m0 + ty * 4 + i) : (m0 + 64 + ty * 4 + (i - 4));
        if (m < M) {
            float2 p0 = unpack2(cc[i][0]), p1 = unpack2(cc[i][1]);
            float2 p2 = unpack2(cc[i][2]), p3 = unpack2(cc[i][3]);
            float4 r0 = make_float4(p0.x + bv0.x, p0.y + bv0.y, p1.x + bv0.z, p1.y + bv0.w);
            float4 r1 = make_float4(p2.x + bv1.x, p2.y + bv1.y, p3.x + bv1.z, p3.y + bv1.w);
            *(float4*)&C[(size_t)m * ldc + n0 + tx * 4] = r0;
            *(float4*)&C[(size_t)m * ldc + n0 + 64 + tx * 4] = r1;
        }
    }
}

// ---------------- epilogue S: structural score for all edges ----------------
__global__ void k_epiS(const void* __restrict__ edge, const int* __restrict__ mask,
                       const float* __restrict__ sw2, const float* __restrict__ sb2,
                       float* __restrict__ out)
{
    int w = (blockIdx.x * blockDim.x + threadIdx.x) >> 5;
    int lane = threadIdx.x & 31;
    if (w >= E_EDGES) return;
    const float* h = &g_Hs[(size_t)w * NS_PAD];
    float v0 = fmaxf(h[lane], 0.0f), v1 = fmaxf(h[lane + 32], 0.0f);
    float part = v0 * sw2[lane] + v1 * sw2[lane + 32];
    #pragma unroll
    for (int o = 16; o > 0; o >>= 1) part += __shfl_xor_sync(0xffffffffu, part, o);
    float ss = part + sb2[0];
    if (lane == 0) {
        g_ss[w] = ss;
        int s, d;
        read_edge(edge, w, s, d);
        if (!(mask[s] != 0 && mask[d] != 0)) out[w] = ss;
    }
}

// ---------------- epilogue C: chemical + combined scores, blend ----------------
__global__ void k_epiC(const float* __restrict__ cw2, const float* __restrict__ cb2,
                       const float* __restrict__ mw2, const float* __restrict__ mb2,
                       float* __restrict__ out)
{
    int w = (blockIdx.x * blockDim.x + threadIdx.x) >> 5;
    int lane = threadIdx.x & 31;
    if (w >= g_count) return;
    const float* h = &g_Hc[(size_t)w * NC_PAD];
    float sc = 0.0f, sm = 0.0f;
    #pragma unroll
    for (int i = 0; i < 6; i++) {
        int j = lane + 32 * i;
        sc += fmaxf(h[j], 0.0f) * cw2[j];
    }
    #pragma unroll
    for (int i = 0; i < 4; i++) {
        int j = lane + 32 * i;
        sm += fmaxf(h[192 + j], 0.0f) * mw2[j];
    }
    #pragma unroll
    for (int o = 16; o > 0; o >>= 1) {
        sc += __shfl_xor_sync(0xffffffffu, sc, o);
        sm += __shfl_xor_sync(0xffffffffu, sm, o);
    }
    if (lane == 0) {
        float schem = sc + cb2[0];
        float scomb = sm + mb2[0];
        int e = g_outidx[w];
        out[e] = g_w[0] * g_ss[e] + g_w[1] * schem + g_w[2] * scomb;
    }
}

// ---------------- launcher ----------------
extern "C" void kernel_launch(void* const* d_in, const int* in_sizes, int n_in,
                              void* d_out, int out_size)
{
    const float* z    = (const float*)d_in[0];
    const float* chem = (const float*)d_in[1];
    const void*  edge = d_in[2];
    const int*   mask = (const int*)d_in[3];
    const float* sw1 = (const float*)d_in[4];
    const float* sb1 = (const float*)d_in[5];
    const float* sw2 = (const float*)d_in[6];
    const float* sb2 = (const float*)d_in[7];
    const float* cw1 = (const float*)d_in[8];
    const float* cb1 = (const float*)d_in[9];
    const float* cw2 = (const float*)d_in[10];
    const float* cb2 = (const float*)d_in[11];
    const float* mw1 = (const float*)d_in[12];
    const float* mb1 = (const float*)d_in[13];
    const float* mw2 = (const float*)d_in[14];
    const float* mb2 = (const float*)d_in[15];
    const float* pw  = (const float*)d_in[16];
    float* out = (float*)d_out;

    const int mtiles = (E_EDGES + 127) / 128;  // 1563

    k_pack<<<1408, 256>>>(cw1, cb1, mw1, mb1, sw1, sb1, pw, edge);
    k_gather<<<(E_EDGES + 7) / 8, 256>>>(z, chem, edge, mask);
    k_sgemm<0><<<dim3(mtiles, 1), 256>>>();
    k_epiS<<<(E_EDGES + 7) / 8, 256>>>(edge, mask, sw2, sb2, out);
    k_sgemm<1><<<dim3(mtiles, 3), 256>>>();
    k_epiC<<<(E_EDGES + 7) / 8, 256>>>(cw2, cb2, mw2, mb2, out);
}